// round 7
// baseline (speedup 1.0000x reference)
#include <cuda_runtime.h>
#include <cuda_fp16.h>
#include <mma.h>
#include <cstdint>

using namespace nvcuda;

#define BS   4
#define TN   512
#define DM   512
#define HN   8
#define HDN  64
#define LN_  6
#define VN   50257
#define VNP  50304          // VN padded to multiple of 128
#define EPSV 1e-5f

// ---------------- scratch ----------------
__device__ float  g_h   [BS*TN*DM];          // residual stream (fp32)
__device__ float  g_qkv [BS*TN*3*DM];        // qkv activations (fp32, read by attention)
__device__ float  g_sc  [BS*HN*TN*TN];       // attention scores
__device__ __half g_tmpH[BS*TN*DM];          // LN output (fp16, GEMM A)
__device__ __half g_attH[BS*TN*DM];          // attention output (fp16, GEMM A)
__device__ __half g_ffH [BS*TN*4*DM];        // ff1 output (fp16, GEMM A)
// fp16 weights ([K,N] row-major)
__device__ __half g_qkvH[LN_*DM*3*DM];
__device__ __half g_outH[LN_*DM*DM];
__device__ __half g_ff1H[LN_*DM*4*DM];
__device__ __half g_ff2H[LN_*4*DM*DM];
__device__ __half g_headH[DM*VNP];           // zero-padded

// ---------------- weight conversion ----------------
__global__ void convh_k(const float* __restrict__ src, __half* __restrict__ dst, int n) {
    int i = blockIdx.x * 256 + threadIdx.x;
    if (i < n) dst[i] = __float2half(src[i]);
}
__global__ void convpad_k(const float* __restrict__ src, __half* __restrict__ dst) {
    int n = blockIdx.x * 256 + threadIdx.x;
    int k = blockIdx.y;
    if (n < VNP)
        dst[(size_t)k * VNP + n] = (n < VN) ? __float2half(src[(size_t)k * VN + n]) : __half(0.0f);
}

// ---------------- embedding ----------------
__global__ void embed_k(const int* __restrict__ x, const float* __restrict__ tok,
                        const float* __restrict__ pos, float* __restrict__ h) {
    int i = blockIdx.x * 256 + threadIdx.x;
    if (i >= BS*TN*DM) return;
    int d  = i % DM;
    int bt = i / DM;
    int t  = bt % TN;
    h[i] = tok[(size_t)x[bt] * DM + d] + pos[t * DM + d];
}

// ---------------- layernorm: fp32 in -> fp16 out ----------------
__global__ __launch_bounds__(256) void ln_k(const float* __restrict__ in, __half* __restrict__ out,
                                            const float* __restrict__ sc, const float* __restrict__ bi) {
    __shared__ float s1[256], s2[256];
    int row = blockIdx.x;
    int tid = threadIdx.x;
    const float* xr = in + (size_t)row * DM;
    float a = xr[tid], b = xr[tid + 256];
    s1[tid] = a + b;
    s2[tid] = a * a + b * b;
    __syncthreads();
    for (int s = 128; s > 0; s >>= 1) {
        if (tid < s) { s1[tid] += s1[tid + s]; s2[tid] += s2[tid + s]; }
        __syncthreads();
    }
    float mean = s1[0] * (1.0f / DM);
    float var  = s2[0] * (1.0f / DM) - mean * mean;
    float r    = rsqrtf(var + EPSV);
    out[(size_t)row * DM + tid]       = __float2half((a - mean) * r * sc[tid]       + bi[tid]);
    out[(size_t)row * DM + tid + 256] = __float2half((b - mean) * r * sc[tid + 256] + bi[tid + 256]);
}

// ---------------- epilogue store helpers ----------------
__device__ __forceinline__ void stval(float* C, size_t i, float v)  { C[i] = v; }
__device__ __forceinline__ void stval(__half* C, size_t i, float v) { C[i] = __float2half(v); }

// ---------------- fp16 wmma GEMM, 3-stage cp.async, 1 barrier per K-step ----------------
// C[M,N] = A[M,K](fp16) @ B[K,N](fp16) + bias (+epilogue), fp32 accumulate.
// MODE 0: bias; 1: bias + exact gelu; 2: bias + residual.
// Bs = B row stride (>= N, multiple of 8). 16B-aligned cp.async by construction.
template <int BM, int BN, int WR, int WC, int MODE, typename OT>
__global__ __launch_bounds__(256) void gemmh2(const __half* __restrict__ A,
                                              const __half* __restrict__ B,
                                              const float* __restrict__ bias,
                                              const float* __restrict__ res,
                                              OT* __restrict__ C,
                                              int M, int N, int K, int Bs) {
    constexpr int BK  = 32;
    constexpr int ST  = 3;
    constexpr int LDA = BK + 8;        // 40 halves, 80B rows (16B-aligned chunk bases)
    constexpr int LDB = BN + 8;
    constexpr int WTM = BM / WR;
    constexpr int WTN = BN / WC;
    constexpr int FM  = WTM / 16;
    constexpr int FN  = WTN / 16;
    constexpr int SZA = BM * LDA;      // halves per A stage
    constexpr int SZB = BK * LDB;      // halves per B stage
    constexpr int IA  = (BM * BK / 8) / 256;   // 16B chunks per thread (A)
    constexpr int CHB = BN / 8;
    constexpr int IB  = (BK * CHB) / 256;      // 16B chunks per thread (B)

    extern __shared__ char dsm[];
    __half* smA = (__half*)dsm;
    __half* smB = smA + ST * SZA;

    const int tid  = threadIdx.x;
    const int warp = tid >> 5;
    const int lane = tid & 31;
    const int wm   = warp / WC;
    const int wn   = warp % WC;
    const int m0   = blockIdx.x * BM;
    const int n0   = blockIdx.y * BN;

    const uint32_t sA0 = (uint32_t)__cvta_generic_to_shared(smA);
    const uint32_t sB0 = (uint32_t)__cvta_generic_to_shared(smB);

    wmma::fragment<wmma::accumulator, 16, 16, 16, float> acc[FM][FN];
    #pragma unroll
    for (int i = 0; i < FM; i++)
        #pragma unroll
        for (int j = 0; j < FN; j++)
            wmma::fill_fragment(acc[i][j], 0.0f);

    auto issue = [&](int buf, int k0) {
        #pragma unroll
        for (int i = 0; i < IA; i++) {
            int idx = tid + i * 256;
            int r = idx >> 2, c = (idx & 3) * 8;
            uint32_t dst = sA0 + (uint32_t)(buf * SZA + r * LDA + c) * 2u;
            const __half* src = A + (size_t)(m0 + r) * K + k0 + c;
            asm volatile("cp.async.cg.shared.global [%0], [%1], 16;" :: "r"(dst), "l"(src));
        }
        #pragma unroll
        for (int i = 0; i < IB; i++) {
            int idx = tid + i * 256;
            int r = idx / CHB, c = (idx % CHB) * 8;
            uint32_t dst = sB0 + (uint32_t)(buf * SZB + r * LDB + c) * 2u;
            const __half* src = B + (size_t)(k0 + r) * Bs + n0 + c;
            asm volatile("cp.async.cg.shared.global [%0], [%1], 16;" :: "r"(dst), "l"(src));
        }
    };

    const int nst = K / BK;

    issue(0, 0);
    asm volatile("cp.async.commit_group;" ::: "memory");
    issue(1, BK);
    asm volatile("cp.async.commit_group;" ::: "memory");

    for (int s = 0; s < nst; s++) {
        asm volatile("cp.async.wait_group 1;" ::: "memory");
        __syncthreads();

        if (s + 2 < nst) issue((s + 2) % ST, (s + 2) * BK);
        asm volatile("cp.async.commit_group;" ::: "memory");

        const int buf = s % ST;
        const __half* pa = smA + buf * SZA;
        const __half* pb = smB + buf * SZB;
        #pragma unroll
        for (int ks = 0; ks < BK; ks += 16) {
            wmma::fragment<wmma::matrix_a, 16, 16, 16, __half, wmma::row_major> af[FM];
            wmma::fragment<wmma::matrix_b, 16, 16, 16, __half, wmma::row_major> bf[FN];
            #pragma unroll
            for (int i = 0; i < FM; i++)
                wmma::load_matrix_sync(af[i], pa + (wm * WTM + i * 16) * LDA + ks, LDA);
            #pragma unroll
            for (int j = 0; j < FN; j++)
                wmma::load_matrix_sync(bf[j], pb + ks * LDB + wn * WTN + j * 16, LDB);
            #pragma unroll
            for (int i = 0; i < FM; i++)
                #pragma unroll
                for (int j = 0; j < FN; j++)
                    wmma::mma_sync(acc[i][j], af[i], bf[j], acc[i][j]);
        }
    }
    __syncthreads();    // pipeline smem dead; epilogue aliases it

    // fused epilogue via per-warp smem patch
    float* patch = (float*)dsm + warp * (16 * 20);
    #pragma unroll
    for (int i = 0; i < FM; i++)
        #pragma unroll
        for (int j = 0; j < FN; j++) {
            wmma::store_matrix_sync(patch, acc[i][j], 20, wmma::mem_row_major);
            __syncwarp();
            const int rg0 = m0 + wm * WTM + i * 16;
            const int cg0 = n0 + wn * WTN + j * 16;
            #pragma unroll
            for (int e = 0; e < 8; e++) {
                int li  = lane * 8 + e;
                int r   = li >> 4;
                int c   = li & 15;
                int col = cg0 + c;
                if (col < N) {
                    size_t gi = (size_t)(rg0 + r) * N + col;
                    float v = patch[r * 20 + c] + bias[col];
                    if (MODE == 1) v = 0.5f * v * (1.0f + erff(v * 0.70710678118654752f));
                    if (MODE == 2) v += res[gi];
                    stval(C, gi, v);
                }
            }
            __syncwarp();
        }
}

// smem sizes (bytes) for the two tile configs
#define GSM(BM_, BN_) (3 * ((BM_) * (32 + 8) + 32 * ((BN_) + 8)) * 2)

// ---------------- attention: S = Q K^T * scale, causal (masked tiles not written) ----------------
__global__ __launch_bounds__(256) void scores_k(const float* __restrict__ qkv, float* __restrict__ sc) {
    int bh = blockIdx.z;
    int b  = bh >> 3;
    int h  = bh & 7;
    int q0 = blockIdx.y << 6;
    int j0 = blockIdx.x << 6;
    if (j0 > q0) return;
    float* out = sc + (size_t)bh * TN * TN;
    int tid = threadIdx.x;

    __shared__ float Qs[64][65], Ks[64][65];
    #pragma unroll
    for (int r = 0; r < 16; r++) {
        int idx = r * 256 + tid;
        int rr = idx >> 6, cc = idx & 63;
        Qs[rr][cc] = qkv[((size_t)(b * TN + q0 + rr)) * 1536 + h * 64 + cc];
        Ks[rr][cc] = qkv[((size_t)(b * TN + j0 + rr)) * 1536 + 512 + h * 64 + cc];
    }
    __syncthreads();

    int tx = tid & 15, ty = tid >> 4;
    float acc[4][4] = {};
    #pragma unroll 8
    for (int d = 0; d < 64; d++) {
        float a0 = Qs[ty * 4 + 0][d], a1 = Qs[ty * 4 + 1][d], a2 = Qs[ty * 4 + 2][d], a3 = Qs[ty * 4 + 3][d];
        float b0 = Ks[tx * 4 + 0][d], b1 = Ks[tx * 4 + 1][d], b2 = Ks[tx * 4 + 2][d], b3 = Ks[tx * 4 + 3][d];
        acc[0][0] += a0 * b0; acc[0][1] += a0 * b1; acc[0][2] += a0 * b2; acc[0][3] += a0 * b3;
        acc[1][0] += a1 * b0; acc[1][1] += a1 * b1; acc[1][2] += a1 * b2; acc[1][3] += a1 * b3;
        acc[2][0] += a2 * b0; acc[2][1] += a2 * b1; acc[2][2] += a2 * b2; acc[2][3] += a2 * b3;
        acc[3][0] += a3 * b0; acc[3][1] += a3 * b1; acc[3][2] += a3 * b2; acc[3][3] += a3 * b3;
    }
    #pragma unroll
    for (int i = 0; i < 4; i++)
        #pragma unroll
        for (int j = 0; j < 4; j++) {
            int row = q0 + ty * 4 + i;
            int col = j0 + tx * 4 + j;
            out[(size_t)row * TN + col] = (col <= row) ? acc[i][j] * 0.125f : -1e30f;
        }
}

// ---------------- softmax (causal: only touches up to diagonal tile) ----------------
__global__ __launch_bounds__(256) void softmax_k(float* __restrict__ sc) {
    int warp = threadIdx.x >> 5, lane = threadIdx.x & 31;
    size_t row = (size_t)blockIdx.x * 8 + warp;
    int r = (int)(row & (TN - 1));
    int imax = (((r >> 6) + 1) << 1);
    float* p = sc + row * TN;
    float v[16];
    float mx = -3.4e38f;
    #pragma unroll
    for (int i = 0; i < 16; i++) {
        v[i] = (i < imax) ? p[lane + 32 * i] : -3.4e38f;
        mx = fmaxf(mx, v[i]);
    }
    #pragma unroll
    for (int o = 16; o; o >>= 1) mx = fmaxf(mx, __shfl_xor_sync(0xffffffffu, mx, o));
    float s = 0.0f;
    #pragma unroll
    for (int i = 0; i < 16; i++) {
        v[i] = (i < imax) ? expf(v[i] - mx) : 0.0f;
        s += v[i];
    }
    #pragma unroll
    for (int o = 16; o; o >>= 1) s += __shfl_xor_sync(0xffffffffu, s, o);
    float inv = 1.0f / s;
    #pragma unroll
    for (int i = 0; i < 16; i++)
        if (i < imax) p[lane + 32 * i] = v[i] * inv;
}

// ---------------- O = P @ V  (fp16 output for proj GEMM) ----------------
__global__ __launch_bounds__(256) void av_k(const float* __restrict__ sc, const float* __restrict__ qkv,
                                            __half* __restrict__ o) {
    int bh = blockIdx.z;
    int b  = bh >> 3;
    int h  = bh & 7;
    int q0 = blockIdx.y << 6;
    const float* P = sc + (size_t)bh * TN * TN;

    __shared__ float Ps[64][65], Vs[64][65];
    int tid = threadIdx.x;
    int tx = tid & 15, ty = tid >> 4;
    float acc[4][4] = {};

    for (int k0 = 0; k0 <= q0; k0 += 64) {
        #pragma unroll
        for (int r = 0; r < 16; r++) {
            int idx = r * 256 + tid;
            int rr = idx >> 6, cc = idx & 63;
            Ps[rr][cc] = P[(size_t)(q0 + rr) * TN + k0 + cc];
            Vs[rr][cc] = qkv[((size_t)(b * TN + k0 + rr)) * 1536 + 1024 + h * 64 + cc];
        }
        __syncthreads();
        #pragma unroll 8
        for (int kk = 0; kk < 64; kk++) {
            float a0 = Ps[ty * 4 + 0][kk], a1 = Ps[ty * 4 + 1][kk], a2 = Ps[ty * 4 + 2][kk], a3 = Ps[ty * 4 + 3][kk];
            float b0 = Vs[kk][tx * 4 + 0], b1 = Vs[kk][tx * 4 + 1], b2 = Vs[kk][tx * 4 + 2], b3 = Vs[kk][tx * 4 + 3];
            acc[0][0] += a0 * b0; acc[0][1] += a0 * b1; acc[0][2] += a0 * b2; acc[0][3] += a0 * b3;
            acc[1][0] += a1 * b0; acc[1][1] += a1 * b1; acc[1][2] += a1 * b2; acc[1][3] += a1 * b3;
            acc[2][0] += a2 * b0; acc[2][1] += a2 * b1; acc[2][2] += a2 * b2; acc[2][3] += a2 * b3;
            acc[3][0] += a3 * b0; acc[3][1] += a3 * b1; acc[3][2] += a3 * b2; acc[3][3] += a3 * b3;
        }
        __syncthreads();
    }
    #pragma unroll
    for (int i = 0; i < 4; i++)
        #pragma unroll
        for (int j = 0; j < 4; j++)
            o[((size_t)(b * TN + q0 + ty * 4 + i)) * DM + h * 64 + tx * 4 + j] =
                __float2half(acc[i][j]);
}

// ---------------- launch ----------------
extern "C" void kernel_launch(void* const* d_in, const int* in_sizes, int n_in,
                              void* d_out, int out_size) {
    const int*   x      = (const int*)  d_in[0];
    const float* tok    = (const float*)d_in[1];
    const float* pos    = (const float*)d_in[2];
    const float* qkv_w  = (const float*)d_in[3];
    const float* qkv_b  = (const float*)d_in[4];
    const float* out_w  = (const float*)d_in[5];
    const float* out_b  = (const float*)d_in[6];
    const float* ln1_s  = (const float*)d_in[7];
    const float* ln1_b  = (const float*)d_in[8];
    const float* ff1_w  = (const float*)d_in[9];
    const float* ff1_b  = (const float*)d_in[10];
    const float* ff2_w  = (const float*)d_in[11];
    const float* ff2_b  = (const float*)d_in[12];
    const float* ln2_s  = (const float*)d_in[13];
    const float* ln2_b  = (const float*)d_in[14];
    const float* lnf_s  = (const float*)d_in[15];
    const float* lnf_b  = (const float*)d_in[16];
    const float* head_w = (const float*)d_in[17];
    const float* head_b = (const float*)d_in[18];
    float* out = (float*)d_out;

    float *h, *qkv, *sc;
    __half *tmpH, *attH, *ffH, *qkvH, *outH, *ff1H, *ff2H, *headH;
    cudaGetSymbolAddress((void**)&h,    g_h);
    cudaGetSymbolAddress((void**)&qkv,  g_qkv);
    cudaGetSymbolAddress((void**)&sc,   g_sc);
    cudaGetSymbolAddress((void**)&tmpH, g_tmpH);
    cudaGetSymbolAddress((void**)&attH, g_attH);
    cudaGetSymbolAddress((void**)&ffH,  g_ffH);
    cudaGetSymbolAddress((void**)&qkvH, g_qkvH);
    cudaGetSymbolAddress((void**)&outH, g_outH);
    cudaGetSymbolAddress((void**)&ff1H, g_ff1H);
    cudaGetSymbolAddress((void**)&ff2H, g_ff2H);
    cudaGetSymbolAddress((void**)&headH,g_headH);

    const int M = BS * TN;  // 2048
    const int SMBIG = GSM(128, 128);   // 56832 B
    const int SMSML = GSM(64, 64);     // 29184 B

    cudaFuncSetAttribute(gemmh2<128,128,4,2,0,float>,  cudaFuncAttributeMaxDynamicSharedMemorySize, SMBIG);
    cudaFuncSetAttribute(gemmh2<128,128,4,2,1,__half>, cudaFuncAttributeMaxDynamicSharedMemorySize, SMBIG);
    cudaFuncSetAttribute(gemmh2<64,64,2,4,2,float>,    cudaFuncAttributeMaxDynamicSharedMemorySize, SMSML);

    // weight conversions (fp32 -> fp16)
    {
        int n;
        n = LN_*DM*3*DM;   convh_k<<<(n+255)/256, 256>>>(qkv_w, qkvH, n);
        n = LN_*DM*DM;     convh_k<<<(n+255)/256, 256>>>(out_w, outH, n);
        n = LN_*DM*4*DM;   convh_k<<<(n+255)/256, 256>>>(ff1_w, ff1H, n);
        n = LN_*4*DM*DM;   convh_k<<<(n+255)/256, 256>>>(ff2_w, ff2H, n);
        convpad_k<<<dim3((VNP+255)/256, DM), 256>>>(head_w, headH);
    }

    embed_k<<<(BS*TN*DM + 255) / 256, 256>>>(x, tok, pos, h);

    for (int l = 0; l < LN_; l++) {
        const __half* wq = qkvH + (size_t)l * DM * 3*DM;
        const __half* wo = outH + (size_t)l * DM * DM;
        const __half* w1 = ff1H + (size_t)l * DM * 4*DM;
        const __half* w2 = ff2H + (size_t)l * 4*DM * DM;
        const float* bq = qkv_b + (size_t)l * 3*DM;
        const float* bo = out_b + (size_t)l * DM;
        const float* b1 = ff1_b + (size_t)l * 4*DM;
        const float* b2 = ff2_b + (size_t)l * DM;

        // attention block
        ln_k<<<M, 256>>>(h, tmpH, ln1_s + l * DM, ln1_b + l * DM);
        gemmh2<128,128,4,2,0,float><<<dim3(16, 12), 256, SMBIG>>>(tmpH, wq, bq, nullptr, qkv, M, 3*DM, DM, 3*DM);
        scores_k<<<dim3(8, 8, 32), 256>>>(qkv, sc);
        softmax_k<<<(BS * HN * TN) / 8, 256>>>(sc);
        av_k<<<dim3(1, 8, 32), 256>>>(sc, qkv, attH);
        gemmh2<64,64,2,4,2,float><<<dim3(32, 8), 256, SMSML>>>(attH, wo, bo, h, h, M, DM, DM, DM);

        // feed-forward block
        ln_k<<<M, 256>>>(h, tmpH, ln2_s + l * DM, ln2_b + l * DM);
        gemmh2<128,128,4,2,1,__half><<<dim3(16, 16), 256, SMBIG>>>(tmpH, w1, b1, nullptr, ffH, M, 4*DM, DM, 4*DM);
        gemmh2<64,64,2,4,2,float><<<dim3(32, 8), 256, SMSML>>>(ffH, w2, b2, h, h, M, DM, 4*DM, DM);
    }

    // final LN + LM head (B padded to VNP; C guarded by col < VN)
    ln_k<<<M, 256>>>(h, tmpH, lnf_s, lnf_b);
    gemmh2<128,128,4,2,0,float><<<dim3(16, VNP / 128), 256, SMBIG>>>(tmpH, headH, head_b, nullptr, out, M, VN, DM, VNP);
}

// round 8
// speedup vs baseline: 1.1294x; 1.1294x over previous
#include <cuda_runtime.h>
#include <cuda_fp16.h>
#include <mma.h>
#include <cstdint>

using namespace nvcuda;

#define BS   4
#define TN   512
#define DM   512
#define HN   8
#define HDN  64
#define LN_  6
#define VN   50257
#define VNP  50304          // VN padded to multiple of 128
#define EPSV 1e-5f

// ---------------- scratch ----------------
__device__ float  g_h   [BS*TN*DM];          // residual stream (fp32)
__device__ float  g_qkv [BS*TN*3*DM];        // qkv activations (fp32, read by attention)
__device__ float  g_sc  [BS*HN*TN*TN];       // attention scores
__device__ __half g_tmpH[BS*TN*DM];          // LN output (fp16, GEMM A)
__device__ __half g_attH[BS*TN*DM];          // attention output (fp16, GEMM A)
__device__ __half g_ffH [BS*TN*4*DM];        // ff1 output (fp16, GEMM A)
// fp16 weights ([K,N] row-major)
__device__ __half g_qkvH[LN_*DM*3*DM];
__device__ __half g_outH[LN_*DM*DM];
__device__ __half g_ff1H[LN_*DM*4*DM];
__device__ __half g_ff2H[LN_*4*DM*DM];
__device__ __half g_headH[DM*VNP];           // zero-padded

// ---------------- weight conversion (vectorized: 4 elems/thread) ----------------
__global__ void convh_k(const float* __restrict__ src, __half* __restrict__ dst, int n4) {
    int i = blockIdx.x * 256 + threadIdx.x;
    if (i >= n4) return;
    float4 v = *(const float4*)&src[i * 4];
    __half2* d = (__half2*)&dst[i * 4];
    d[0] = __floats2half2_rn(v.x, v.y);
    d[1] = __floats2half2_rn(v.z, v.w);
}
__global__ void convpad_k(const float* __restrict__ src, __half* __restrict__ dst) {
    int n = (blockIdx.x * 256 + threadIdx.x) * 4;
    int k = blockIdx.y;
    if (n >= VNP) return;
    const float* sp = src + (size_t)k * VN;
    float a = (n + 0 < VN) ? sp[n + 0] : 0.0f;
    float b = (n + 1 < VN) ? sp[n + 1] : 0.0f;
    float c = (n + 2 < VN) ? sp[n + 2] : 0.0f;
    float d = (n + 3 < VN) ? sp[n + 3] : 0.0f;
    __half2* dp = (__half2*)&dst[(size_t)k * VNP + n];
    dp[0] = __floats2half2_rn(a, b);
    dp[1] = __floats2half2_rn(c, d);
}

// ---------------- embedding ----------------
__global__ void embed_k(const int* __restrict__ x, const float* __restrict__ tok,
                        const float* __restrict__ pos, float* __restrict__ h) {
    int i = blockIdx.x * 256 + threadIdx.x;
    if (i >= BS*TN*DM) return;
    int d  = i % DM;
    int bt = i / DM;
    int t  = bt % TN;
    h[i] = tok[(size_t)x[bt] * DM + d] + pos[t * DM + d];
}

// ---------------- layernorm: fp32 in -> fp16 out ----------------
__global__ __launch_bounds__(256) void ln_k(const float* __restrict__ in, __half* __restrict__ out,
                                            const float* __restrict__ sc, const float* __restrict__ bi) {
    __shared__ float s1[256], s2[256];
    int row = blockIdx.x;
    int tid = threadIdx.x;
    const float* xr = in + (size_t)row * DM;
    float a = xr[tid], b = xr[tid + 256];
    s1[tid] = a + b;
    s2[tid] = a * a + b * b;
    __syncthreads();
    for (int s = 128; s > 0; s >>= 1) {
        if (tid < s) { s1[tid] += s1[tid + s]; s2[tid] += s2[tid + s]; }
        __syncthreads();
    }
    float mean = s1[0] * (1.0f / DM);
    float var  = s2[0] * (1.0f / DM) - mean * mean;
    float r    = rsqrtf(var + EPSV);
    out[(size_t)row * DM + tid]       = __float2half((a - mean) * r * sc[tid]       + bi[tid]);
    out[(size_t)row * DM + tid + 256] = __float2half((b - mean) * r * sc[tid + 256] + bi[tid + 256]);
}

// ---------------- epilogue store helpers ----------------
__device__ __forceinline__ void stval(float* C, size_t i, float v)  { C[i] = v; }
__device__ __forceinline__ void stval(__half* C, size_t i, float v) { C[i] = __float2half(v); }

// ---------------- fp16 wmma GEMM, 2-stage cp.async (round-6 core, generalized) ----------------
// C[M,N] = A[M,K](fp16) @ B[K,N](fp16) + bias (+epilogue), fp32 accumulate.
// MODE 0: bias; 1: bias + exact gelu; 2: bias + residual.
// Bs = B row stride (>= N, multiple of 8). 16B-aligned cp.async by construction.
template <int BM, int BN, int NT, int WR, int WC, int MODE, typename OT>
__global__ __launch_bounds__(NT) void gemmh(const __half* __restrict__ A,
                                            const __half* __restrict__ B,
                                            const float* __restrict__ bias,
                                            const float* __restrict__ res,
                                            OT* __restrict__ C,
                                            int M, int N, int K, int Bs) {
    constexpr int BK  = 32;
    constexpr int LDA = BK + 8;            // 40 halves, 80B rows
    constexpr int LDB = BN + 8;
    constexpr int NW  = NT / 32;
    constexpr int WTM = BM / WR;
    constexpr int WTN = BN / WC;
    constexpr int FM  = WTM / 16;
    constexpr int FN  = WTN / 16;
    constexpr int IA  = (BM * BK / 8) / NT;   // 16B chunks per thread (A)
    constexpr int CHB = BN / 8;
    constexpr int IB  = (BK * CHB) / NT;      // 16B chunks per thread (B)

    __shared__ union SMU {
        struct { __half A[2][BM * LDA]; __half B[2][BK * LDB]; } p;
        float epi[NW][16 * 20];
    } sm;

    const int tid  = threadIdx.x;
    const int warp = tid >> 5;
    const int lane = tid & 31;
    const int wm   = warp / WC;
    const int wn   = warp % WC;
    const int m0   = blockIdx.x * BM;
    const int n0   = blockIdx.y * BN;

    const uint32_t sA0 = (uint32_t)__cvta_generic_to_shared(&sm.p.A[0][0]);
    const uint32_t sB0 = (uint32_t)__cvta_generic_to_shared(&sm.p.B[0][0]);

    wmma::fragment<wmma::accumulator, 16, 16, 16, float> acc[FM][FN];
    #pragma unroll
    for (int i = 0; i < FM; i++)
        #pragma unroll
        for (int j = 0; j < FN; j++)
            wmma::fill_fragment(acc[i][j], 0.0f);

    auto issue = [&](int buf, int k0) {
        #pragma unroll
        for (int i = 0; i < IA; i++) {
            int idx = tid + i * NT;
            int r = idx >> 2, c = (idx & 3) * 8;
            uint32_t dst = sA0 + (uint32_t)(buf * BM * LDA + r * LDA + c) * 2u;
            const __half* src = A + (size_t)(m0 + r) * K + k0 + c;
            asm volatile("cp.async.cg.shared.global [%0], [%1], 16;" :: "r"(dst), "l"(src));
        }
        #pragma unroll
        for (int i = 0; i < IB; i++) {
            int idx = tid + i * NT;
            int r = idx / CHB, c = (idx % CHB) * 8;
            uint32_t dst = sB0 + (uint32_t)(buf * BK * LDB + r * LDB + c) * 2u;
            const __half* src = B + (size_t)(k0 + r) * Bs + n0 + c;
            asm volatile("cp.async.cg.shared.global [%0], [%1], 16;" :: "r"(dst), "l"(src));
        }
    };

    const int nst = K / BK;

    issue(0, 0);
    asm volatile("cp.async.commit_group;" ::: "memory");

    for (int s = 0; s < nst; s++) {
        if (s + 1 < nst) {
            issue((s + 1) & 1, (s + 1) * BK);
            asm volatile("cp.async.commit_group;" ::: "memory");
            asm volatile("cp.async.wait_group 1;" ::: "memory");
        } else {
            asm volatile("cp.async.wait_group 0;" ::: "memory");
        }
        __syncthreads();

        const int buf = s & 1;
        #pragma unroll
        for (int ks = 0; ks < BK; ks += 16) {
            wmma::fragment<wmma::matrix_a, 16, 16, 16, __half, wmma::row_major> af[FM];
            wmma::fragment<wmma::matrix_b, 16, 16, 16, __half, wmma::row_major> bf[FN];
            #pragma unroll
            for (int i = 0; i < FM; i++)
                wmma::load_matrix_sync(af[i], &sm.p.A[buf][(wm * WTM + i * 16) * LDA + ks], LDA);
            #pragma unroll
            for (int j = 0; j < FN; j++)
                wmma::load_matrix_sync(bf[j], &sm.p.B[buf][ks * LDB + wn * WTN + j * 16], LDB);
            #pragma unroll
            for (int i = 0; i < FM; i++)
                #pragma unroll
                for (int j = 0; j < FN; j++)
                    wmma::mma_sync(acc[i][j], af[i], bf[j], acc[i][j]);
        }
        __syncthreads();
    }

    // fused epilogue via per-warp smem patch (pipeline smem is dead)
    float* patch = &sm.epi[warp][0];
    #pragma unroll
    for (int i = 0; i < FM; i++)
        #pragma unroll
        for (int j = 0; j < FN; j++) {
            wmma::store_matrix_sync(patch, acc[i][j], 20, wmma::mem_row_major);
            __syncwarp();
            const int rg0 = m0 + wm * WTM + i * 16;
            const int cg0 = n0 + wn * WTN + j * 16;
            #pragma unroll
            for (int e = 0; e < 8; e++) {
                int li  = lane * 8 + e;
                int r   = li >> 4;
                int c   = li & 15;
                int col = cg0 + c;
                if (col < N) {
                    size_t gi = (size_t)(rg0 + r) * N + col;
                    float v = patch[r * 20 + c] + bias[col];
                    if (MODE == 1) v = 0.5f * v * (1.0f + erff(v * 0.70710678118654752f));
                    if (MODE == 2) v += res[gi];
                    stval(C, gi, v);
                }
            }
            __syncwarp();
        }
}

// ---------------- attention: S = Q K^T * scale, causal (masked tiles not written) ----------------
__global__ __launch_bounds__(256) void scores_k(const float* __restrict__ qkv, float* __restrict__ sc) {
    int bh = blockIdx.z;
    int b  = bh >> 3;
    int h  = bh & 7;
    int q0 = blockIdx.y << 6;
    int j0 = blockIdx.x << 6;
    if (j0 > q0) return;
    float* out = sc + (size_t)bh * TN * TN;
    int tid = threadIdx.x;

    __shared__ float Qs[64][65], Ks[64][65];
    #pragma unroll
    for (int r = 0; r < 16; r++) {
        int idx = r * 256 + tid;
        int rr = idx >> 6, cc = idx & 63;
        Qs[rr][cc] = qkv[((size_t)(b * TN + q0 + rr)) * 1536 + h * 64 + cc];
        Ks[rr][cc] = qkv[((size_t)(b * TN + j0 + rr)) * 1536 + 512 + h * 64 + cc];
    }
    __syncthreads();

    int tx = tid & 15, ty = tid >> 4;
    float acc[4][4] = {};
    #pragma unroll 8
    for (int d = 0; d < 64; d++) {
        float a0 = Qs[ty * 4 + 0][d], a1 = Qs[ty * 4 + 1][d], a2 = Qs[ty * 4 + 2][d], a3 = Qs[ty * 4 + 3][d];
        float b0 = Ks[tx * 4 + 0][d], b1 = Ks[tx * 4 + 1][d], b2 = Ks[tx * 4 + 2][d], b3 = Ks[tx * 4 + 3][d];
        acc[0][0] += a0 * b0; acc[0][1] += a0 * b1; acc[0][2] += a0 * b2; acc[0][3] += a0 * b3;
        acc[1][0] += a1 * b0; acc[1][1] += a1 * b1; acc[1][2] += a1 * b2; acc[1][3] += a1 * b3;
        acc[2][0] += a2 * b0; acc[2][1] += a2 * b1; acc[2][2] += a2 * b2; acc[2][3] += a2 * b3;
        acc[3][0] += a3 * b0; acc[3][1] += a3 * b1; acc[3][2] += a3 * b2; acc[3][3] += a3 * b3;
    }
    #pragma unroll
    for (int i = 0; i < 4; i++)
        #pragma unroll
        for (int j = 0; j < 4; j++) {
            int row = q0 + ty * 4 + i;
            int col = j0 + tx * 4 + j;
            out[(size_t)row * TN + col] = (col <= row) ? acc[i][j] * 0.125f : -1e30f;
        }
}

// ---------------- softmax (causal: only touches up to diagonal tile) ----------------
__global__ __launch_bounds__(256) void softmax_k(float* __restrict__ sc) {
    int warp = threadIdx.x >> 5, lane = threadIdx.x & 31;
    size_t row = (size_t)blockIdx.x * 8 + warp;
    int r = (int)(row & (TN - 1));
    int imax = (((r >> 6) + 1) << 1);
    float* p = sc + row * TN;
    float v[16];
    float mx = -3.4e38f;
    #pragma unroll
    for (int i = 0; i < 16; i++) {
        v[i] = (i < imax) ? p[lane + 32 * i] : -3.4e38f;
        mx = fmaxf(mx, v[i]);
    }
    #pragma unroll
    for (int o = 16; o; o >>= 1) mx = fmaxf(mx, __shfl_xor_sync(0xffffffffu, mx, o));
    float s = 0.0f;
    #pragma unroll
    for (int i = 0; i < 16; i++) {
        v[i] = (i < imax) ? expf(v[i] - mx) : 0.0f;
        s += v[i];
    }
    #pragma unroll
    for (int o = 16; o; o >>= 1) s += __shfl_xor_sync(0xffffffffu, s, o);
    float inv = 1.0f / s;
    #pragma unroll
    for (int i = 0; i < 16; i++)
        if (i < imax) p[lane + 32 * i] = v[i] * inv;
}

// ---------------- O = P @ V  (fp16 output for proj GEMM) ----------------
__global__ __launch_bounds__(256) void av_k(const float* __restrict__ sc, const float* __restrict__ qkv,
                                            __half* __restrict__ o) {
    int bh = blockIdx.z;
    int b  = bh >> 3;
    int h  = bh & 7;
    int q0 = blockIdx.y << 6;
    const float* P = sc + (size_t)bh * TN * TN;

    __shared__ float Ps[64][65], Vs[64][65];
    int tid = threadIdx.x;
    int tx = tid & 15, ty = tid >> 4;
    float acc[4][4] = {};

    for (int k0 = 0; k0 <= q0; k0 += 64) {
        #pragma unroll
        for (int r = 0; r < 16; r++) {
            int idx = r * 256 + tid;
            int rr = idx >> 6, cc = idx & 63;
            Ps[rr][cc] = P[(size_t)(q0 + rr) * TN + k0 + cc];
            Vs[rr][cc] = qkv[((size_t)(b * TN + k0 + rr)) * 1536 + 1024 + h * 64 + cc];
        }
        __syncthreads();
        #pragma unroll 8
        for (int kk = 0; kk < 64; kk++) {
            float a0 = Ps[ty * 4 + 0][kk], a1 = Ps[ty * 4 + 1][kk], a2 = Ps[ty * 4 + 2][kk], a3 = Ps[ty * 4 + 3][kk];
            float b0 = Vs[kk][tx * 4 + 0], b1 = Vs[kk][tx * 4 + 1], b2 = Vs[kk][tx * 4 + 2], b3 = Vs[kk][tx * 4 + 3];
            acc[0][0] += a0 * b0; acc[0][1] += a0 * b1; acc[0][2] += a0 * b2; acc[0][3] += a0 * b3;
            acc[1][0] += a1 * b0; acc[1][1] += a1 * b1; acc[1][2] += a1 * b2; acc[1][3] += a1 * b3;
            acc[2][0] += a2 * b0; acc[2][1] += a2 * b1; acc[2][2] += a2 * b2; acc[2][3] += a2 * b3;
            acc[3][0] += a3 * b0; acc[3][1] += a3 * b1; acc[3][2] += a3 * b2; acc[3][3] += a3 * b3;
        }
        __syncthreads();
    }
    #pragma unroll
    for (int i = 0; i < 4; i++)
        #pragma unroll
        for (int j = 0; j < 4; j++)
            o[((size_t)(b * TN + q0 + ty * 4 + i)) * DM + h * 64 + tx * 4 + j] =
                __float2half(acc[i][j]);
}

// ---------------- launch ----------------
extern "C" void kernel_launch(void* const* d_in, const int* in_sizes, int n_in,
                              void* d_out, int out_size) {
    const int*   x      = (const int*)  d_in[0];
    const float* tok    = (const float*)d_in[1];
    const float* pos    = (const float*)d_in[2];
    const float* qkv_w  = (const float*)d_in[3];
    const float* qkv_b  = (const float*)d_in[4];
    const float* out_w  = (const float*)d_in[5];
    const float* out_b  = (const float*)d_in[6];
    const float* ln1_s  = (const float*)d_in[7];
    const float* ln1_b  = (const float*)d_in[8];
    const float* ff1_w  = (const float*)d_in[9];
    const float* ff1_b  = (const float*)d_in[10];
    const float* ff2_w  = (const float*)d_in[11];
    const float* ff2_b  = (const float*)d_in[12];
    const float* ln2_s  = (const float*)d_in[13];
    const float* ln2_b  = (const float*)d_in[14];
    const float* lnf_s  = (const float*)d_in[15];
    const float* lnf_b  = (const float*)d_in[16];
    const float* head_w = (const float*)d_in[17];
    const float* head_b = (const float*)d_in[18];
    float* out = (float*)d_out;

    float *h, *qkv, *sc;
    __half *tmpH, *attH, *ffH, *qkvH, *outH, *ff1H, *ff2H, *headH;
    cudaGetSymbolAddress((void**)&h,    g_h);
    cudaGetSymbolAddress((void**)&qkv,  g_qkv);
    cudaGetSymbolAddress((void**)&sc,   g_sc);
    cudaGetSymbolAddress((void**)&tmpH, g_tmpH);
    cudaGetSymbolAddress((void**)&attH, g_attH);
    cudaGetSymbolAddress((void**)&ffH,  g_ffH);
    cudaGetSymbolAddress((void**)&qkvH, g_qkvH);
    cudaGetSymbolAddress((void**)&outH, g_outH);
    cudaGetSymbolAddress((void**)&ff1H, g_ff1H);
    cudaGetSymbolAddress((void**)&ff2H, g_ff2H);
    cudaGetSymbolAddress((void**)&headH,g_headH);

    const int M = BS * TN;  // 2048

    // weight conversions (fp32 -> fp16), 4 elems/thread
    {
        int n4;
        n4 = LN_*DM*3*DM/4;  convh_k<<<(n4+255)/256, 256>>>(qkv_w, qkvH, n4);
        n4 = LN_*DM*DM/4;    convh_k<<<(n4+255)/256, 256>>>(out_w, outH, n4);
        n4 = LN_*DM*4*DM/4;  convh_k<<<(n4+255)/256, 256>>>(ff1_w, ff1H, n4);
        n4 = LN_*4*DM*DM/4;  convh_k<<<(n4+255)/256, 256>>>(ff2_w, ff2H, n4);
        convpad_k<<<dim3((VNP/4+255)/256, DM), 256>>>(head_w, headH);
    }

    embed_k<<<(BS*TN*DM + 255) / 256, 256>>>(x, tok, pos, h);

    for (int l = 0; l < LN_; l++) {
        const __half* wq = qkvH + (size_t)l * DM * 3*DM;
        const __half* wo = outH + (size_t)l * DM * DM;
        const __half* w1 = ff1H + (size_t)l * DM * 4*DM;
        const __half* w2 = ff2H + (size_t)l * 4*DM * DM;
        const float* bq = qkv_b + (size_t)l * 3*DM;
        const float* bo = out_b + (size_t)l * DM;
        const float* b1 = ff1_b + (size_t)l * 4*DM;
        const float* b2 = ff2_b + (size_t)l * DM;

        // attention block
        ln_k<<<M, 256>>>(h, tmpH, ln1_s + l * DM, ln1_b + l * DM);
        gemmh<128,128,256,4,2,0,float><<<dim3(16, 12), 256>>>(tmpH, wq, bq, nullptr, qkv, M, 3*DM, DM, 3*DM);
        scores_k<<<dim3(8, 8, 32), 256>>>(qkv, sc);
        softmax_k<<<(BS * HN * TN) / 8, 256>>>(sc);
        av_k<<<dim3(1, 8, 32), 256>>>(sc, qkv, attH);
        gemmh<64,64,128,2,2,2,float><<<dim3(32, 8), 128>>>(attH, wo, bo, h, h, M, DM, DM, DM);

        // feed-forward block
        ln_k<<<M, 256>>>(h, tmpH, ln2_s + l * DM, ln2_b + l * DM);
        gemmh<128,128,256,4,2,1,__half><<<dim3(16, 16), 256>>>(tmpH, w1, b1, nullptr, ffH, M, 4*DM, DM, 4*DM);
        gemmh<64,64,128,2,2,2,float><<<dim3(32, 8), 128>>>(ffH, w2, b2, h, h, M, DM, 4*DM, DM);
    }

    // final LN + LM head (B padded to VNP; C guarded by col < VN)
    ln_k<<<M, 256>>>(h, tmpH, lnf_s, lnf_b);
    gemmh<128,128,256,4,2,0,float><<<dim3(16, VNP / 128), 256>>>(tmpH, headH, head_b, nullptr, out, M, VN, DM, VNP);
}

// round 9
// speedup vs baseline: 1.3017x; 1.1526x over previous
#include <cuda_runtime.h>
#include <cuda_fp16.h>
#include <mma.h>
#include <cstdint>

using namespace nvcuda;

#define BS   4
#define TN   512
#define DM   512
#define HN   8
#define HDN  64
#define LN_  6
#define VN   50257
#define VNP  50304          // VN padded to multiple of 128
#define EPSV 1e-5f

// ---------------- scratch ----------------
__device__ float  g_h   [BS*TN*DM];          // residual stream (fp32)
__device__ __half g_tmpH[BS*TN*DM];          // LN output (fp16, GEMM A)
__device__ __half g_qkvA[BS*TN*3*DM];        // qkv activations (fp16)
__device__ __half g_attH[BS*TN*DM];          // attention output (fp16, GEMM A)
__device__ __half g_ffH [BS*TN*4*DM];        // ff1 output (fp16, GEMM A)
// fp16 weights ([K,N] row-major)
__device__ __half g_qkvH[LN_*DM*3*DM];
__device__ __half g_outH[LN_*DM*DM];
__device__ __half g_ff1H[LN_*DM*4*DM];
__device__ __half g_ff2H[LN_*4*DM*DM];
__device__ __half g_headH[DM*VNP];           // zero-padded

// ---------------- weight conversion (vectorized: 4 elems/thread) ----------------
__global__ void convh_k(const float* __restrict__ src, __half* __restrict__ dst, int n4) {
    int i = blockIdx.x * 256 + threadIdx.x;
    if (i >= n4) return;
    float4 v = *(const float4*)&src[i * 4];
    __half2* d = (__half2*)&dst[i * 4];
    d[0] = __floats2half2_rn(v.x, v.y);
    d[1] = __floats2half2_rn(v.z, v.w);
}
__global__ void convpad_k(const float* __restrict__ src, __half* __restrict__ dst) {
    int n = (blockIdx.x * 256 + threadIdx.x) * 4;
    int k = blockIdx.y;
    if (n >= VNP) return;
    const float* sp = src + (size_t)k * VN;
    float a = (n + 0 < VN) ? sp[n + 0] : 0.0f;
    float b = (n + 1 < VN) ? sp[n + 1] : 0.0f;
    float c = (n + 2 < VN) ? sp[n + 2] : 0.0f;
    float d = (n + 3 < VN) ? sp[n + 3] : 0.0f;
    __half2* dp = (__half2*)&dst[(size_t)k * VNP + n];
    dp[0] = __floats2half2_rn(a, b);
    dp[1] = __floats2half2_rn(c, d);
}

// ---------------- embedding ----------------
__global__ void embed_k(const int* __restrict__ x, const float* __restrict__ tok,
                        const float* __restrict__ pos, float* __restrict__ h) {
    int i = blockIdx.x * 256 + threadIdx.x;
    if (i >= BS*TN*DM) return;
    int d  = i % DM;
    int bt = i / DM;
    int t  = bt % TN;
    h[i] = tok[(size_t)x[bt] * DM + d] + pos[t * DM + d];
}

// ---------------- layernorm: warp per row, 8 rows/CTA ----------------
__global__ __launch_bounds__(256) void ln_k(const float* __restrict__ in, __half* __restrict__ out,
                                            const float* __restrict__ sc, const float* __restrict__ bi) {
    int warp = threadIdx.x >> 5, lane = threadIdx.x & 31;
    int row = blockIdx.x * 8 + warp;
    const float4* xr = (const float4*)(in + (size_t)row * DM);
    float4 v[4];
    float s1 = 0.0f, s2 = 0.0f;
    #pragma unroll
    for (int i = 0; i < 4; i++) {
        v[i] = xr[lane + i * 32];
        s1 += v[i].x + v[i].y + v[i].z + v[i].w;
        s2 += v[i].x*v[i].x + v[i].y*v[i].y + v[i].z*v[i].z + v[i].w*v[i].w;
    }
    #pragma unroll
    for (int o = 16; o; o >>= 1) {
        s1 += __shfl_xor_sync(0xffffffffu, s1, o);
        s2 += __shfl_xor_sync(0xffffffffu, s2, o);
    }
    float mean = s1 * (1.0f / DM);
    float r = rsqrtf(s2 * (1.0f / DM) - mean * mean + EPSV);
    const float4* sc4 = (const float4*)sc;
    const float4* bi4 = (const float4*)bi;
    __half2* op = (__half2*)(out + (size_t)row * DM);
    #pragma unroll
    for (int i = 0; i < 4; i++) {
        int ch = lane + i * 32;
        float4 g = sc4[ch], bb = bi4[ch];
        float4 x = v[i];
        op[ch * 2]     = __floats2half2_rn((x.x - mean) * r * g.x + bb.x,
                                           (x.y - mean) * r * g.y + bb.y);
        op[ch * 2 + 1] = __floats2half2_rn((x.z - mean) * r * g.z + bb.z,
                                           (x.w - mean) * r * g.w + bb.w);
    }
}

// ---------------- epilogue store helpers ----------------
__device__ __forceinline__ void stval(float* C, size_t i, float v)  { C[i] = v; }
__device__ __forceinline__ void stval(__half* C, size_t i, float v) { C[i] = __float2half(v); }

// ---------------- fp16 wmma GEMM, 2-stage cp.async ----------------
template <int BM, int BN, int NT, int WR, int WC, int MODE, typename OT>
__global__ __launch_bounds__(NT) void gemmh(const __half* __restrict__ A,
                                            const __half* __restrict__ B,
                                            const float* __restrict__ bias,
                                            const float* __restrict__ res,
                                            OT* __restrict__ C,
                                            int M, int N, int K, int Bs) {
    constexpr int BK  = 32;
    constexpr int LDA = BK + 8;
    constexpr int LDB = BN + 8;
    constexpr int NW  = NT / 32;
    constexpr int WTM = BM / WR;
    constexpr int WTN = BN / WC;
    constexpr int FM  = WTM / 16;
    constexpr int FN  = WTN / 16;
    constexpr int IA  = (BM * BK / 8) / NT;
    constexpr int CHB = BN / 8;
    constexpr int IB  = (BK * CHB) / NT;

    __shared__ union SMU {
        struct { __half A[2][BM * LDA]; __half B[2][BK * LDB]; } p;
        float epi[NW][16 * 20];
    } sm;

    const int tid  = threadIdx.x;
    const int warp = tid >> 5;
    const int lane = tid & 31;
    const int wm   = warp / WC;
    const int wn   = warp % WC;
    const int m0   = blockIdx.x * BM;
    const int n0   = blockIdx.y * BN;

    const uint32_t sA0 = (uint32_t)__cvta_generic_to_shared(&sm.p.A[0][0]);
    const uint32_t sB0 = (uint32_t)__cvta_generic_to_shared(&sm.p.B[0][0]);

    wmma::fragment<wmma::accumulator, 16, 16, 16, float> acc[FM][FN];
    #pragma unroll
    for (int i = 0; i < FM; i++)
        #pragma unroll
        for (int j = 0; j < FN; j++)
            wmma::fill_fragment(acc[i][j], 0.0f);

    auto issue = [&](int buf, int k0) {
        #pragma unroll
        for (int i = 0; i < IA; i++) {
            int idx = tid + i * NT;
            int r = idx >> 2, c = (idx & 3) * 8;
            uint32_t dst = sA0 + (uint32_t)(buf * BM * LDA + r * LDA + c) * 2u;
            const __half* src = A + (size_t)(m0 + r) * K + k0 + c;
            asm volatile("cp.async.cg.shared.global [%0], [%1], 16;" :: "r"(dst), "l"(src));
        }
        #pragma unroll
        for (int i = 0; i < IB; i++) {
            int idx = tid + i * NT;
            int r = idx / CHB, c = (idx % CHB) * 8;
            uint32_t dst = sB0 + (uint32_t)(buf * BK * LDB + r * LDB + c) * 2u;
            const __half* src = B + (size_t)(k0 + r) * Bs + n0 + c;
            asm volatile("cp.async.cg.shared.global [%0], [%1], 16;" :: "r"(dst), "l"(src));
        }
    };

    const int nst = K / BK;

    issue(0, 0);
    asm volatile("cp.async.commit_group;" ::: "memory");

    for (int s = 0; s < nst; s++) {
        if (s + 1 < nst) {
            issue((s + 1) & 1, (s + 1) * BK);
            asm volatile("cp.async.commit_group;" ::: "memory");
            asm volatile("cp.async.wait_group 1;" ::: "memory");
        } else {
            asm volatile("cp.async.wait_group 0;" ::: "memory");
        }
        __syncthreads();

        const int buf = s & 1;
        #pragma unroll
        for (int ks = 0; ks < BK; ks += 16) {
            wmma::fragment<wmma::matrix_a, 16, 16, 16, __half, wmma::row_major> af[FM];
            wmma::fragment<wmma::matrix_b, 16, 16, 16, __half, wmma::row_major> bf[FN];
            #pragma unroll
            for (int i = 0; i < FM; i++)
                wmma::load_matrix_sync(af[i], &sm.p.A[buf][(wm * WTM + i * 16) * LDA + ks], LDA);
            #pragma unroll
            for (int j = 0; j < FN; j++)
                wmma::load_matrix_sync(bf[j], &sm.p.B[buf][ks * LDB + wn * WTN + j * 16], LDB);
            #pragma unroll
            for (int i = 0; i < FM; i++)
                #pragma unroll
                for (int j = 0; j < FN; j++)
                    wmma::mma_sync(acc[i][j], af[i], bf[j], acc[i][j]);
        }
        __syncthreads();
    }

    float* patch = &sm.epi[warp][0];
    #pragma unroll
    for (int i = 0; i < FM; i++)
        #pragma unroll
        for (int j = 0; j < FN; j++) {
            wmma::store_matrix_sync(patch, acc[i][j], 20, wmma::mem_row_major);
            __syncwarp();
            const int rg0 = m0 + wm * WTM + i * 16;
            const int cg0 = n0 + wn * WTN + j * 16;
            #pragma unroll
            for (int e = 0; e < 8; e++) {
                int li  = lane * 8 + e;
                int r   = li >> 4;
                int c   = li & 15;
                int col = cg0 + c;
                if (col < N) {
                    size_t gi = (size_t)(rg0 + r) * N + col;
                    float v = patch[r * 20 + c] + bias[col];
                    if (MODE == 1) v = 0.5f * v * (1.0f + erff(v * 0.70710678118654752f));
                    if (MODE == 2) v += res[gi];
                    stval(C, gi, v);
                }
            }
            __syncwarp();
        }
}

// ---------------- fused flash attention ----------------
// One CTA = (b, h, 64-row q tile). 4 warps. qkv fp16 in, O fp16 out.
// smem: Qs/Ks/Vs/Ph [64x72] half, Sf/Of [64x68] float, m/l [64] float = 72192 B.
#define ATT_SMEM (4 * 64 * 72 * 2 + 2 * 64 * 68 * 4 + 2 * 64 * 4)

__global__ __launch_bounds__(128) void fattn_k(const __half* __restrict__ qkv,
                                               __half* __restrict__ o) {
    int bh = blockIdx.y;
    int b  = bh >> 3;
    int h  = bh & 7;
    int q0 = blockIdx.x << 6;
    int tid = threadIdx.x, warp = tid >> 5, lane = tid & 31;

    extern __shared__ char smem[];
    __half* Qs = (__half*)smem;             // 64*72
    __half* Ks = Qs + 64 * 72;
    __half* Vs = Ks + 64 * 72;
    __half* Ph = Vs + 64 * 72;
    float*  Sf = (float*)(Ph + 64 * 72);    // 64*68
    float*  Of = Sf + 64 * 68;
    float*  mrow = Of + 64 * 68;
    float*  lrow = mrow + 64;

    const uint32_t sQ = (uint32_t)__cvta_generic_to_shared(Qs);
    const uint32_t sK = (uint32_t)__cvta_generic_to_shared(Ks);
    const uint32_t sV = (uint32_t)__cvta_generic_to_shared(Vs);

    // load Q tile (64 rows x 64 halves): 512 16B-chunks / 128 threads = 4 each
    #pragma unroll
    for (int i = 0; i < 4; i++) {
        int idx = tid + i * 128;
        int r = idx >> 3, c = (idx & 7) * 8;
        uint32_t dst = sQ + (uint32_t)(r * 72 + c) * 2u;
        const __half* src = qkv + ((size_t)(b * TN + q0 + r)) * 1536 + h * 64 + c;
        asm volatile("cp.async.cg.shared.global [%0], [%1], 16;" :: "r"(dst), "l"(src));
    }
    asm volatile("cp.async.commit_group;" ::: "memory");

    for (int i = tid; i < 64 * 68; i += 128) Of[i] = 0.0f;
    if (tid < 64) { mrow[tid] = -1e30f; lrow[tid] = 0.0f; }

    const int jmax = q0 >> 6;
    for (int j = 0; j <= jmax; j++) {
        const int j0 = j << 6;
        // load K, V tiles
        #pragma unroll
        for (int i = 0; i < 4; i++) {
            int idx = tid + i * 128;
            int r = idx >> 3, c = (idx & 7) * 8;
            const __half* srcK = qkv + ((size_t)(b * TN + j0 + r)) * 1536 + 512 + h * 64 + c;
            const __half* srcV = qkv + ((size_t)(b * TN + j0 + r)) * 1536 + 1024 + h * 64 + c;
            uint32_t dK = sK + (uint32_t)(r * 72 + c) * 2u;
            uint32_t dV = sV + (uint32_t)(r * 72 + c) * 2u;
            asm volatile("cp.async.cg.shared.global [%0], [%1], 16;" :: "r"(dK), "l"(srcK));
            asm volatile("cp.async.cg.shared.global [%0], [%1], 16;" :: "r"(dV), "l"(srcV));
        }
        asm volatile("cp.async.commit_group;" ::: "memory");
        asm volatile("cp.async.wait_group 0;" ::: "memory");
        __syncthreads();

        // S = Q @ K^T (fp32 acc), warp w -> rows [w*16, w*16+16)
        {
            wmma::fragment<wmma::matrix_a, 16, 16, 16, __half, wmma::row_major> af;
            wmma::fragment<wmma::matrix_b, 16, 16, 16, __half, wmma::col_major> bf;
            wmma::fragment<wmma::accumulator, 16, 16, 16, float> ac[4];
            #pragma unroll
            for (int n = 0; n < 4; n++) wmma::fill_fragment(ac[n], 0.0f);
            #pragma unroll
            for (int k = 0; k < 4; k++) {
                wmma::load_matrix_sync(af, Qs + (warp * 16) * 72 + k * 16, 72);
                #pragma unroll
                for (int n = 0; n < 4; n++) {
                    wmma::load_matrix_sync(bf, Ks + (n * 16) * 72 + k * 16, 72);
                    wmma::mma_sync(ac[n], af, bf, ac[n]);
                }
            }
            #pragma unroll
            for (int n = 0; n < 4; n++)
                wmma::store_matrix_sync(Sf + (warp * 16) * 68 + n * 16, ac[n], 68,
                                        wmma::mem_row_major);
        }
        __syncthreads();

        // online softmax update: 2 threads per row (32 cols each)
        {
            int r  = tid >> 1;
            int hc = (tid & 1) * 32;
            bool diag = (j == jmax);
            float* srow = Sf + r * 68 + hc;
            float sv[32];
            float lm = -1e30f;
            #pragma unroll
            for (int c = 0; c < 32; c++) {
                float s = srow[c] * 0.125f;
                if (diag && (hc + c) > r) s = -1e30f;
                sv[c] = s;
                lm = fmaxf(lm, s);
            }
            float mt = fmaxf(lm, __shfl_xor_sync(0xffffffffu, lm, 1));
            float mo = mrow[r];
            float mn = fmaxf(mo, mt);
            float fs = expf(mo - mn);
            float sum = 0.0f;
            __half* prow = Ph + r * 72 + hc;
            #pragma unroll
            for (int c = 0; c < 32; c++) {
                float p = expf(sv[c] - mn);
                prow[c] = __float2half(p);
                sum += p;
            }
            sum += __shfl_xor_sync(0xffffffffu, sum, 1);
            float* orow = Of + r * 68 + hc;
            #pragma unroll
            for (int c = 0; c < 32; c++) orow[c] *= fs;
            __syncwarp();
            if ((tid & 1) == 0) {
                mrow[r] = mn;
                lrow[r] = lrow[r] * fs + sum;
            }
        }
        __syncthreads();

        // O += P @ V
        {
            wmma::fragment<wmma::matrix_a, 16, 16, 16, __half, wmma::row_major> af;
            wmma::fragment<wmma::matrix_b, 16, 16, 16, __half, wmma::row_major> bf;
            wmma::fragment<wmma::accumulator, 16, 16, 16, float> ac;
            #pragma unroll
            for (int n = 0; n < 4; n++) {
                wmma::load_matrix_sync(ac, Of + (warp * 16) * 68 + n * 16, 68,
                                       wmma::mem_row_major);
                #pragma unroll
                for (int k = 0; k < 4; k++) {
                    wmma::load_matrix_sync(af, Ph + (warp * 16) * 72 + k * 16, 72);
                    wmma::load_matrix_sync(bf, Vs + (k * 16) * 72 + n * 16, 72);
                    wmma::mma_sync(ac, af, bf, ac);
                }
                wmma::store_matrix_sync(Of + (warp * 16) * 68 + n * 16, ac, 68,
                                        wmma::mem_row_major);
            }
        }
        __syncthreads();
    }

    // epilogue: O / l -> fp16
    {
        int r  = tid >> 1;
        int hc = (tid & 1) * 32;
        float inv = 1.0f / lrow[r];
        float* orow = Of + r * 68 + hc;
        __half* dst = o + ((size_t)(b * TN + q0 + r)) * DM + h * 64 + hc;
        #pragma unroll
        for (int c = 0; c < 32; c++)
            dst[c] = __float2half(orow[c] * inv);
    }
}

// ---------------- launch ----------------
extern "C" void kernel_launch(void* const* d_in, const int* in_sizes, int n_in,
                              void* d_out, int out_size) {
    const int*   x      = (const int*)  d_in[0];
    const float* tok    = (const float*)d_in[1];
    const float* pos    = (const float*)d_in[2];
    const float* qkv_w  = (const float*)d_in[3];
    const float* qkv_b  = (const float*)d_in[4];
    const float* out_w  = (const float*)d_in[5];
    const float* out_b  = (const float*)d_in[6];
    const float* ln1_s  = (const float*)d_in[7];
    const float* ln1_b  = (const float*)d_in[8];
    const float* ff1_w  = (const float*)d_in[9];
    const float* ff1_b  = (const float*)d_in[10];
    const float* ff2_w  = (const float*)d_in[11];
    const float* ff2_b  = (const float*)d_in[12];
    const float* ln2_s  = (const float*)d_in[13];
    const float* ln2_b  = (const float*)d_in[14];
    const float* lnf_s  = (const float*)d_in[15];
    const float* lnf_b  = (const float*)d_in[16];
    const float* head_w = (const float*)d_in[17];
    const float* head_b = (const float*)d_in[18];
    float* out = (float*)d_out;

    float *h;
    __half *tmpH, *qkvA, *attH, *ffH, *qkvH, *outH, *ff1H, *ff2H, *headH;
    cudaGetSymbolAddress((void**)&h,    g_h);
    cudaGetSymbolAddress((void**)&tmpH, g_tmpH);
    cudaGetSymbolAddress((void**)&qkvA, g_qkvA);
    cudaGetSymbolAddress((void**)&attH, g_attH);
    cudaGetSymbolAddress((void**)&ffH,  g_ffH);
    cudaGetSymbolAddress((void**)&qkvH, g_qkvH);
    cudaGetSymbolAddress((void**)&outH, g_outH);
    cudaGetSymbolAddress((void**)&ff1H, g_ff1H);
    cudaGetSymbolAddress((void**)&ff2H, g_ff2H);
    cudaGetSymbolAddress((void**)&headH,g_headH);

    const int M = BS * TN;  // 2048

    cudaFuncSetAttribute(fattn_k, cudaFuncAttributeMaxDynamicSharedMemorySize, ATT_SMEM);

    // weight conversions (fp32 -> fp16), 4 elems/thread
    {
        int n4;
        n4 = LN_*DM*3*DM/4;  convh_k<<<(n4+255)/256, 256>>>(qkv_w, qkvH, n4);
        n4 = LN_*DM*DM/4;    convh_k<<<(n4+255)/256, 256>>>(out_w, outH, n4);
        n4 = LN_*DM*4*DM/4;  convh_k<<<(n4+255)/256, 256>>>(ff1_w, ff1H, n4);
        n4 = LN_*4*DM*DM/4;  convh_k<<<(n4+255)/256, 256>>>(ff2_w, ff2H, n4);
        convpad_k<<<dim3((VNP/4+255)/256, DM), 256>>>(head_w, headH);
    }

    embed_k<<<(BS*TN*DM + 255) / 256, 256>>>(x, tok, pos, h);

    for (int l = 0; l < LN_; l++) {
        const __half* wq = qkvH + (size_t)l * DM * 3*DM;
        const __half* wo = outH + (size_t)l * DM * DM;
        const __half* w1 = ff1H + (size_t)l * DM * 4*DM;
        const __half* w2 = ff2H + (size_t)l * 4*DM * DM;
        const float* bq = qkv_b + (size_t)l * 3*DM;
        const float* bo = out_b + (size_t)l * DM;
        const float* b1 = ff1_b + (size_t)l * 4*DM;
        const float* b2 = ff2_b + (size_t)l * DM;

        // attention block
        ln_k<<<M / 8, 256>>>(h, tmpH, ln1_s + l * DM, ln1_b + l * DM);
        gemmh<128,128,256,4,2,0,__half><<<dim3(16, 12), 256>>>(tmpH, wq, bq, nullptr, qkvA, M, 3*DM, DM, 3*DM);
        fattn_k<<<dim3(8, 32), 128, ATT_SMEM>>>(qkvA, attH);
        gemmh<64,64,128,2,2,2,float><<<dim3(32, 8), 128>>>(attH, wo, bo, h, h, M, DM, DM, DM);

        // feed-forward block
        ln_k<<<M / 8, 256>>>(h, tmpH, ln2_s + l * DM, ln2_b + l * DM);
        gemmh<128,128,256,4,2,1,__half><<<dim3(16, 16), 256>>>(tmpH, w1, b1, nullptr, ffH, M, 4*DM, DM, 4*DM);
        gemmh<64,64,128,2,2,2,float><<<dim3(32, 8), 128>>>(ffH, w2, b2, h, h, M, DM, 4*DM, DM);
    }

    // final LN + LM head (B padded to VNP; C guarded by col < VN)
    ln_k<<<M / 8, 256>>>(h, tmpH, lnf_s, lnf_b);
    gemmh<128,128,256,4,2,0,float><<<dim3(16, VNP / 128), 256>>>(tmpH, headH, head_b, nullptr, out, M, VN, DM, VNP);
}

// round 10
// speedup vs baseline: 1.5198x; 1.1676x over previous
#include <cuda_runtime.h>
#include <cuda_fp16.h>
#include <mma.h>
#include <cstdint>

using namespace nvcuda;

#define BS   4
#define TN   512
#define DM   512
#define HN   8
#define HDN  64
#define LN_  6
#define VN   50257
#define VNP  50304          // VN padded to multiple of 128
#define EPSV 1e-5f

// ---------------- scratch ----------------
__device__ float  g_h   [BS*TN*DM];          // residual stream (fp32)
__device__ __half g_tmpH[BS*TN*DM];          // LN output (fp16, GEMM A)
__device__ __half g_qkvA[BS*TN*3*DM];        // qkv activations (fp16)
__device__ __half g_attH[BS*TN*DM];          // attention output (fp16, GEMM A)
__device__ __half g_ffH [BS*TN*4*DM];        // ff1 output (fp16, GEMM A)
// fp16 weights ([K,N] row-major)
__device__ __half g_qkvH[LN_*DM*3*DM];
__device__ __half g_outH[LN_*DM*DM];
__device__ __half g_ff1H[LN_*DM*4*DM];
__device__ __half g_ff2H[LN_*4*DM*DM];
__device__ __half g_headH[DM*VNP];           // zero-padded

// ---------------- weight conversion (vectorized: 4 elems/thread) ----------------
__global__ void convh_k(const float* __restrict__ src, __half* __restrict__ dst, int n4) {
    int i = blockIdx.x * 256 + threadIdx.x;
    if (i >= n4) return;
    float4 v = *(const float4*)&src[i * 4];
    __half2* d = (__half2*)&dst[i * 4];
    d[0] = __floats2half2_rn(v.x, v.y);
    d[1] = __floats2half2_rn(v.z, v.w);
}
__global__ void convpad_k(const float* __restrict__ src, __half* __restrict__ dst) {
    int n = (blockIdx.x * 256 + threadIdx.x) * 4;
    int k = blockIdx.y;
    if (n >= VNP) return;
    const float* sp = src + (size_t)k * VN;
    float a = (n + 0 < VN) ? sp[n + 0] : 0.0f;
    float b = (n + 1 < VN) ? sp[n + 1] : 0.0f;
    float c = (n + 2 < VN) ? sp[n + 2] : 0.0f;
    float d = (n + 3 < VN) ? sp[n + 3] : 0.0f;
    __half2* dp = (__half2*)&dst[(size_t)k * VNP + n];
    dp[0] = __floats2half2_rn(a, b);
    dp[1] = __floats2half2_rn(c, d);
}

// ---------------- embedding ----------------
__global__ void embed_k(const int* __restrict__ x, const float* __restrict__ tok,
                        const float* __restrict__ pos, float* __restrict__ h) {
    int i = blockIdx.x * 256 + threadIdx.x;
    if (i >= BS*TN*DM) return;
    int d  = i % DM;
    int bt = i / DM;
    int t  = bt % TN;
    h[i] = tok[(size_t)x[bt] * DM + d] + pos[t * DM + d];
}

// ---------------- layernorm: warp per row, 8 rows/CTA ----------------
__global__ __launch_bounds__(256) void ln_k(const float* __restrict__ in, __half* __restrict__ out,
                                            const float* __restrict__ sc, const float* __restrict__ bi) {
    int warp = threadIdx.x >> 5, lane = threadIdx.x & 31;
    int row = blockIdx.x * 8 + warp;
    const float4* xr = (const float4*)(in + (size_t)row * DM);
    float4 v[4];
    float s1 = 0.0f, s2 = 0.0f;
    #pragma unroll
    for (int i = 0; i < 4; i++) {
        v[i] = xr[lane + i * 32];
        s1 += v[i].x + v[i].y + v[i].z + v[i].w;
        s2 += v[i].x*v[i].x + v[i].y*v[i].y + v[i].z*v[i].z + v[i].w*v[i].w;
    }
    #pragma unroll
    for (int o = 16; o; o >>= 1) {
        s1 += __shfl_xor_sync(0xffffffffu, s1, o);
        s2 += __shfl_xor_sync(0xffffffffu, s2, o);
    }
    float mean = s1 * (1.0f / DM);
    float r = rsqrtf(s2 * (1.0f / DM) - mean * mean + EPSV);
    const float4* sc4 = (const float4*)sc;
    const float4* bi4 = (const float4*)bi;
    __half2* op = (__half2*)(out + (size_t)row * DM);
    #pragma unroll
    for (int i = 0; i < 4; i++) {
        int ch = lane + i * 32;
        float4 g = sc4[ch], bb = bi4[ch];
        float4 x = v[i];
        op[ch * 2]     = __floats2half2_rn((x.x - mean) * r * g.x + bb.x,
                                           (x.y - mean) * r * g.y + bb.y);
        op[ch * 2 + 1] = __floats2half2_rn((x.z - mean) * r * g.z + bb.z,
                                           (x.w - mean) * r * g.w + bb.w);
    }
}

// ---------------- epilogue store helpers ----------------
__device__ __forceinline__ void stval(float* C, size_t i, float v)  { C[i] = v; }
__device__ __forceinline__ void stval(__half* C, size_t i, float v) { C[i] = __float2half(v); }

// ---------------- fp16 wmma GEMM, 2-stage cp.async ----------------
// C[M,N] = A[M,K](fp16) @ B[K,N](fp16) + bias (+epilogue), fp32 accumulate.
// MODE 0: bias; 1: bias + exact gelu; 2: bias + residual.
// Bs = B row stride (>= N, multiple of 8). 16B-aligned cp.async by construction.
template <int BM, int BN, int NT, int WR, int WC, int MODE, typename OT>
__global__ __launch_bounds__(NT) void gemmh(const __half* __restrict__ A,
                                            const __half* __restrict__ B,
                                            const float* __restrict__ bias,
                                            const float* __restrict__ res,
                                            OT* __restrict__ C,
                                            int M, int N, int K, int Bs) {
    constexpr int BK  = 32;
    constexpr int LDA = BK + 8;
    constexpr int LDB = BN + 8;
    constexpr int NW  = NT / 32;
    constexpr int WTM = BM / WR;
    constexpr int WTN = BN / WC;
    constexpr int FM  = WTM / 16;
    constexpr int FN  = WTN / 16;
    constexpr int IA  = (BM * BK / 8) / NT;
    constexpr int CHB = BN / 8;
    constexpr int IB  = (BK * CHB) / NT;

    __shared__ union SMU {
        struct { __half A[2][BM * LDA]; __half B[2][BK * LDB]; } p;
        float epi[NW][16 * 20];
    } sm;

    const int tid  = threadIdx.x;
    const int warp = tid >> 5;
    const int lane = tid & 31;
    const int wm   = warp / WC;
    const int wn   = warp % WC;
    const int m0   = blockIdx.x * BM;
    const int n0   = blockIdx.y * BN;

    const uint32_t sA0 = (uint32_t)__cvta_generic_to_shared(&sm.p.A[0][0]);
    const uint32_t sB0 = (uint32_t)__cvta_generic_to_shared(&sm.p.B[0][0]);

    wmma::fragment<wmma::accumulator, 16, 16, 16, float> acc[FM][FN];
    #pragma unroll
    for (int i = 0; i < FM; i++)
        #pragma unroll
        for (int j = 0; j < FN; j++)
            wmma::fill_fragment(acc[i][j], 0.0f);

    auto issue = [&](int buf, int k0) {
        #pragma unroll
        for (int i = 0; i < IA; i++) {
            int idx = tid + i * NT;
            int r = idx >> 2, c = (idx & 3) * 8;
            uint32_t dst = sA0 + (uint32_t)(buf * BM * LDA + r * LDA + c) * 2u;
            const __half* src = A + (size_t)(m0 + r) * K + k0 + c;
            asm volatile("cp.async.cg.shared.global [%0], [%1], 16;" :: "r"(dst), "l"(src));
        }
        #pragma unroll
        for (int i = 0; i < IB; i++) {
            int idx = tid + i * NT;
            int r = idx / CHB, c = (idx % CHB) * 8;
            uint32_t dst = sB0 + (uint32_t)(buf * BK * LDB + r * LDB + c) * 2u;
            const __half* src = B + (size_t)(k0 + r) * Bs + n0 + c;
            asm volatile("cp.async.cg.shared.global [%0], [%1], 16;" :: "r"(dst), "l"(src));
        }
    };

    const int nst = K / BK;

    issue(0, 0);
    asm volatile("cp.async.commit_group;" ::: "memory");

    for (int s = 0; s < nst; s++) {
        if (s + 1 < nst) {
            issue((s + 1) & 1, (s + 1) * BK);
            asm volatile("cp.async.commit_group;" ::: "memory");
            asm volatile("cp.async.wait_group 1;" ::: "memory");
        } else {
            asm volatile("cp.async.wait_group 0;" ::: "memory");
        }
        __syncthreads();

        const int buf = s & 1;
        #pragma unroll
        for (int ks = 0; ks < BK; ks += 16) {
            wmma::fragment<wmma::matrix_a, 16, 16, 16, __half, wmma::row_major> af[FM];
            wmma::fragment<wmma::matrix_b, 16, 16, 16, __half, wmma::row_major> bf[FN];
            #pragma unroll
            for (int i = 0; i < FM; i++)
                wmma::load_matrix_sync(af[i], &sm.p.A[buf][(wm * WTM + i * 16) * LDA + ks], LDA);
            #pragma unroll
            for (int j = 0; j < FN; j++)
                wmma::load_matrix_sync(bf[j], &sm.p.B[buf][ks * LDB + wn * WTN + j * 16], LDB);
            #pragma unroll
            for (int i = 0; i < FM; i++)
                #pragma unroll
                for (int j = 0; j < FN; j++)
                    wmma::mma_sync(acc[i][j], af[i], bf[j], acc[i][j]);
        }
        __syncthreads();
    }

    float* patch = &sm.epi[warp][0];
    #pragma unroll
    for (int i = 0; i < FM; i++)
        #pragma unroll
        for (int j = 0; j < FN; j++) {
            wmma::store_matrix_sync(patch, acc[i][j], 20, wmma::mem_row_major);
            __syncwarp();
            const int rg0 = m0 + wm * WTM + i * 16;
            const int cg0 = n0 + wn * WTN + j * 16;
            #pragma unroll
            for (int e = 0; e < 8; e++) {
                int li  = lane * 8 + e;
                int r   = li >> 4;
                int c   = li & 15;
                int col = cg0 + c;
                if (col < N) {
                    size_t gi = (size_t)(rg0 + r) * N + col;
                    float v = patch[r * 20 + c] + bias[col];
                    if (MODE == 1) v = 0.5f * v * (1.0f + erff(v * 0.70710678118654752f));
                    if (MODE == 2) v += res[gi];
                    stval(C, gi, v);
                }
            }
            __syncwarp();
        }
}

// ---------------- fused flash attention ----------------
// One CTA = (b, h, 64-row q tile). 4 warps. qkv fp16 in, O fp16 out.
#define ATT_SMEM (4 * 64 * 72 * 2 + 2 * 64 * 68 * 4 + 2 * 64 * 4)

__global__ __launch_bounds__(128) void fattn_k(const __half* __restrict__ qkv,
                                               __half* __restrict__ o) {
    int bh = blockIdx.y;
    int b  = bh >> 3;
    int h  = bh & 7;
    int q0 = blockIdx.x << 6;
    int tid = threadIdx.x, warp = tid >> 5, lane = tid & 31;

    extern __shared__ char smem[];
    __half* Qs = (__half*)smem;             // 64*72
    __half* Ks = Qs + 64 * 72;
    __half* Vs = Ks + 64 * 72;
    __half* Ph = Vs + 64 * 72;
    float*  Sf = (float*)(Ph + 64 * 72);    // 64*68
    float*  Of = Sf + 64 * 68;
    float*  mrow = Of + 64 * 68;
    float*  lrow = mrow + 64;

    const uint32_t sQ = (uint32_t)__cvta_generic_to_shared(Qs);
    const uint32_t sK = (uint32_t)__cvta_generic_to_shared(Ks);
    const uint32_t sV = (uint32_t)__cvta_generic_to_shared(Vs);

    #pragma unroll
    for (int i = 0; i < 4; i++) {
        int idx = tid + i * 128;
        int r = idx >> 3, c = (idx & 7) * 8;
        uint32_t dst = sQ + (uint32_t)(r * 72 + c) * 2u;
        const __half* src = qkv + ((size_t)(b * TN + q0 + r)) * 1536 + h * 64 + c;
        asm volatile("cp.async.cg.shared.global [%0], [%1], 16;" :: "r"(dst), "l"(src));
    }
    asm volatile("cp.async.commit_group;" ::: "memory");

    for (int i = tid; i < 64 * 68; i += 128) Of[i] = 0.0f;
    if (tid < 64) { mrow[tid] = -1e30f; lrow[tid] = 0.0f; }

    const int jmax = q0 >> 6;
    for (int j = 0; j <= jmax; j++) {
        const int j0 = j << 6;
        #pragma unroll
        for (int i = 0; i < 4; i++) {
            int idx = tid + i * 128;
            int r = idx >> 3, c = (idx & 7) * 8;
            const __half* srcK = qkv + ((size_t)(b * TN + j0 + r)) * 1536 + 512 + h * 64 + c;
            const __half* srcV = qkv + ((size_t)(b * TN + j0 + r)) * 1536 + 1024 + h * 64 + c;
            uint32_t dK = sK + (uint32_t)(r * 72 + c) * 2u;
            uint32_t dV = sV + (uint32_t)(r * 72 + c) * 2u;
            asm volatile("cp.async.cg.shared.global [%0], [%1], 16;" :: "r"(dK), "l"(srcK));
            asm volatile("cp.async.cg.shared.global [%0], [%1], 16;" :: "r"(dV), "l"(srcV));
        }
        asm volatile("cp.async.commit_group;" ::: "memory");
        asm volatile("cp.async.wait_group 0;" ::: "memory");
        __syncthreads();

        // S = Q @ K^T (fp32 acc), warp w -> rows [w*16, w*16+16)
        {
            wmma::fragment<wmma::matrix_a, 16, 16, 16, __half, wmma::row_major> af;
            wmma::fragment<wmma::matrix_b, 16, 16, 16, __half, wmma::col_major> bf;
            wmma::fragment<wmma::accumulator, 16, 16, 16, float> ac[4];
            #pragma unroll
            for (int n = 0; n < 4; n++) wmma::fill_fragment(ac[n], 0.0f);
            #pragma unroll
            for (int k = 0; k < 4; k++) {
                wmma::load_matrix_sync(af, Qs + (warp * 16) * 72 + k * 16, 72);
                #pragma unroll
                for (int n = 0; n < 4; n++) {
                    wmma::load_matrix_sync(bf, Ks + (n * 16) * 72 + k * 16, 72);
                    wmma::mma_sync(ac[n], af, bf, ac[n]);
                }
            }
            #pragma unroll
            for (int n = 0; n < 4; n++)
                wmma::store_matrix_sync(Sf + (warp * 16) * 68 + n * 16, ac[n], 68,
                                        wmma::mem_row_major);
        }
        __syncthreads();

        // online softmax: 2 threads per row
        {
            int r  = tid >> 1;
            int hc = (tid & 1) * 32;
            bool diag = (j == jmax);
            float* srow = Sf + r * 68 + hc;
            float sv[32];
            float lm = -1e30f;
            #pragma unroll
            for (int c = 0; c < 32; c++) {
                float s = srow[c] * 0.125f;
                if (diag && (hc + c) > r) s = -1e30f;
                sv[c] = s;
                lm = fmaxf(lm, s);
            }
            float mt = fmaxf(lm, __shfl_xor_sync(0xffffffffu, lm, 1));
            float mo = mrow[r];
            float mn = fmaxf(mo, mt);
            float fs = expf(mo - mn);
            float sum = 0.0f;
            __half* prow = Ph + r * 72 + hc;
            #pragma unroll
            for (int c = 0; c < 32; c++) {
                float p = expf(sv[c] - mn);
                prow[c] = __float2half(p);
                sum += p;
            }
            sum += __shfl_xor_sync(0xffffffffu, sum, 1);
            float* orow = Of + r * 68 + hc;
            #pragma unroll
            for (int c = 0; c < 32; c++) orow[c] *= fs;
            __syncwarp();
            if ((tid & 1) == 0) {
                mrow[r] = mn;
                lrow[r] = lrow[r] * fs + sum;
            }
        }
        __syncthreads();

        // O += P @ V
        {
            wmma::fragment<wmma::matrix_a, 16, 16, 16, __half, wmma::row_major> af;
            wmma::fragment<wmma::matrix_b, 16, 16, 16, __half, wmma::row_major> bf;
            wmma::fragment<wmma::accumulator, 16, 16, 16, float> ac;
            #pragma unroll
            for (int n = 0; n < 4; n++) {
                wmma::load_matrix_sync(ac, Of + (warp * 16) * 68 + n * 16, 68,
                                       wmma::mem_row_major);
                #pragma unroll
                for (int k = 0; k < 4; k++) {
                    wmma::load_matrix_sync(af, Ph + (warp * 16) * 72 + k * 16, 72);
                    wmma::load_matrix_sync(bf, Vs + (k * 16) * 72 + n * 16, 72);
                    wmma::mma_sync(ac, af, bf, ac);
                }
                wmma::store_matrix_sync(Of + (warp * 16) * 68 + n * 16, ac, 68,
                                        wmma::mem_row_major);
            }
        }
        __syncthreads();
    }

    // epilogue: O / l -> fp16
    {
        int r  = tid >> 1;
        int hc = (tid & 1) * 32;
        float inv = 1.0f / lrow[r];
        float* orow = Of + r * 68 + hc;
        __half* dst = o + ((size_t)(b * TN + q0 + r)) * DM + h * 64 + hc;
        #pragma unroll
        for (int c = 0; c < 32; c++)
            dst[c] = __float2half(orow[c] * inv);
    }
}

// ---------------- launch ----------------
extern "C" void kernel_launch(void* const* d_in, const int* in_sizes, int n_in,
                              void* d_out, int out_size) {
    const int*   x      = (const int*)  d_in[0];
    const float* tok    = (const float*)d_in[1];
    const float* pos    = (const float*)d_in[2];
    const float* qkv_w  = (const float*)d_in[3];
    const float* qkv_b  = (const float*)d_in[4];
    const float* out_w  = (const float*)d_in[5];
    const float* out_b  = (const float*)d_in[6];
    const float* ln1_s  = (const float*)d_in[7];
    const float* ln1_b  = (const float*)d_in[8];
    const float* ff1_w  = (const float*)d_in[9];
    const float* ff1_b  = (const float*)d_in[10];
    const float* ff2_w  = (const float*)d_in[11];
    const float* ff2_b  = (const float*)d_in[12];
    const float* ln2_s  = (const float*)d_in[13];
    const float* ln2_b  = (const float*)d_in[14];
    const float* lnf_s  = (const float*)d_in[15];
    const float* lnf_b  = (const float*)d_in[16];
    const float* head_w = (const float*)d_in[17];
    const float* head_b = (const float*)d_in[18];
    float* out = (float*)d_out;

    float *h;
    __half *tmpH, *qkvA, *attH, *ffH, *qkvH, *outH, *ff1H, *ff2H, *headH;
    cudaGetSymbolAddress((void**)&h,    g_h);
    cudaGetSymbolAddress((void**)&tmpH, g_tmpH);
    cudaGetSymbolAddress((void**)&qkvA, g_qkvA);
    cudaGetSymbolAddress((void**)&attH, g_attH);
    cudaGetSymbolAddress((void**)&ffH,  g_ffH);
    cudaGetSymbolAddress((void**)&qkvH, g_qkvH);
    cudaGetSymbolAddress((void**)&outH, g_outH);
    cudaGetSymbolAddress((void**)&ff1H, g_ff1H);
    cudaGetSymbolAddress((void**)&ff2H, g_ff2H);
    cudaGetSymbolAddress((void**)&headH,g_headH);

    const int M = BS * TN;  // 2048

    cudaFuncSetAttribute(fattn_k, cudaFuncAttributeMaxDynamicSharedMemorySize, ATT_SMEM);

    // weight conversions (fp32 -> fp16), 4 elems/thread
    {
        int n4;
        n4 = LN_*DM*3*DM/4;  convh_k<<<(n4+255)/256, 256>>>(qkv_w, qkvH, n4);
        n4 = LN_*DM*DM/4;    convh_k<<<(n4+255)/256, 256>>>(out_w, outH, n4);
        n4 = LN_*DM*4*DM/4;  convh_k<<<(n4+255)/256, 256>>>(ff1_w, ff1H, n4);
        n4 = LN_*4*DM*DM/4;  convh_k<<<(n4+255)/256, 256>>>(ff2_w, ff2H, n4);
        convpad_k<<<dim3((VNP/4+255)/256, DM), 256>>>(head_w, headH);
    }

    embed_k<<<(BS*TN*DM + 255) / 256, 256>>>(x, tok, pos, h);

    for (int l = 0; l < LN_; l++) {
        const __half* wq = qkvH + (size_t)l * DM * 3*DM;
        const __half* wo = outH + (size_t)l * DM * DM;
        const __half* w1 = ff1H + (size_t)l * DM * 4*DM;
        const __half* w2 = ff2H + (size_t)l * 4*DM * DM;
        const float* bq = qkv_b + (size_t)l * 3*DM;
        const float* bo = out_b + (size_t)l * DM;
        const float* b1 = ff1_b + (size_t)l * 4*DM;
        const float* b2 = ff2_b + (size_t)l * DM;

        // attention block  (big GEMMs: 4 warps, warp tile 64x64 -> 2x MMA/LDSM ratio)
        ln_k<<<M / 8, 256>>>(h, tmpH, ln1_s + l * DM, ln1_b + l * DM);
        gemmh<128,128,128,2,2,0,__half><<<dim3(16, 12), 128>>>(tmpH, wq, bq, nullptr, qkvA, M, 3*DM, DM, 3*DM);
        fattn_k<<<dim3(8, 32), 128, ATT_SMEM>>>(qkvA, attH);
        gemmh<64,64,128,2,2,2,float><<<dim3(32, 8), 128>>>(attH, wo, bo, h, h, M, DM, DM, DM);

        // feed-forward block
        ln_k<<<M / 8, 256>>>(h, tmpH, ln2_s + l * DM, ln2_b + l * DM);
        gemmh<128,128,128,2,2,1,__half><<<dim3(16, 16), 128>>>(tmpH, w1, b1, nullptr, ffH, M, 4*DM, DM, 4*DM);
        gemmh<64,64,128,2,2,2,float><<<dim3(32, 8), 128>>>(ffH, w2, b2, h, h, M, DM, 4*DM, DM);
    }

    // final LN + LM head
    ln_k<<<M / 8, 256>>>(h, tmpH, lnf_s, lnf_b);
    gemmh<128,128,128,2,2,0,float><<<dim3(16, VNP / 128), 128>>>(tmpH, headH, head_b, nullptr, out, M, VN, DM, VNP);
}